// round 15
// baseline (speedup 1.0000x reference)
#include <cuda_runtime.h>
#include <cuda_fp16.h>
#include <cstdint>
#include <cstddef>

// Problem constants (fixed by the dataset)
#define NN 100000
#define EE 1600000
#define HH 128
#define CCOUT 40
#define SB 98            // ceil(NN/1024) scan blocks
#define NBLK_GEMM 782    // ceil(NN/128)
#define NBLK_HIST 6250   // EE/256
#define NBLK_FILL 6250   // EE/256

// ---------------- scratch (device globals; no allocation allowed) ----------
// Working set per layer: g_hh (25MB gather) + g_h16 (25MB) + g_agg (51MB) +
// csr (6.4MB) = ~108MB < 126MB L2 -> fully L2-resident.
__device__ __half g_h16[(size_t)NN * HH];  // aggregate buffer, fp16 (k_agg output)
__device__ float g_agg[(size_t)NN * HH];   // pre-BN linear output (GEMM writes in-place)
__device__ __half g_hh[(size_t)NN * HH];   // fp16 shadow of pre-BN output (gather source)
__device__ int   g_deg[NN];
__device__ int   g_rowptr[NN + 1];
__device__ int   g_cursor[NN];
__device__ int   g_csr[EE];
__device__ int   g_bsum[SB];
__device__ int   g_boff[SB];
__device__ double g_bnsum[2 * HH];
__device__ float g_scale[HH];
__device__ float g_shift[HH];

// ---------------- fp16 helpers ---------------------------------------------
__device__ __forceinline__ float4 ld_h4(const __half* p) {
    uint2 u = *(const uint2*)p;
    __half2 a = *reinterpret_cast<const __half2*>(&u.x);
    __half2 b = *reinterpret_cast<const __half2*>(&u.y);
    float2 fa = __half22float2(a), fb = __half22float2(b);
    return make_float4(fa.x, fa.y, fb.x, fb.y);
}
__device__ __forceinline__ uint2 pack_h4(float4 v) {
    unsigned short x = __half_as_ushort(__float2half_rn(v.x));
    unsigned short y = __half_as_ushort(__float2half_rn(v.y));
    unsigned short z = __half_as_ushort(__float2half_rn(v.z));
    unsigned short w = __half_as_ushort(__float2half_rn(v.w));
    return make_uint2(((unsigned int)y << 16) | x, ((unsigned int)w << 16) | z);
}

// ---------------- CSR build ------------------------------------------------
// zero g_deg; block 0 also zeroes g_bnsum (for the input-layer GEMM stats)
__global__ void k_zero0() {
    int i = blockIdx.x * blockDim.x + threadIdx.x;
    if (i < NN) g_deg[i] = 0;
    if (blockIdx.x == 0) g_bnsum[threadIdx.x] = 0.0;   // 256 threads = 2*HH
}

__global__ void k_bsum() {
    __shared__ int red[256];
    int b = blockIdx.x, t = threadIdx.x;
    int s = 0;
#pragma unroll
    for (int it = 0; it < 4; it++) {
        int idx = b * 1024 + it * 256 + t;
        if (idx < NN) s += g_deg[idx];
    }
    red[t] = s;
    __syncthreads();
    for (int off = 128; off > 0; off >>= 1) {
        if (t < off) red[t] += red[t + off];
        __syncthreads();
    }
    if (t == 0) g_bsum[b] = red[0];
}

// parallel scan of the 98 block sums
__global__ void k_bscan() {
    __shared__ int s[128];
    int t = threadIdx.x;
    int v = (t < SB) ? g_bsum[t] : 0;
    s[t] = v;
    __syncthreads();
    for (int off = 1; off < 128; off <<= 1) {
        int tv = (t >= off) ? s[t - off] : 0;
        __syncthreads();
        s[t] += tv;
        __syncthreads();
    }
    if (t < SB) g_boff[t] = s[t] - v;   // exclusive
    if (t == 0) g_rowptr[NN] = EE;
}

__global__ void k_scan() {
    __shared__ int s[1024];
    int t = threadIdx.x;
    int idx = blockIdx.x * 1024 + t;
    int v = (idx < NN) ? g_deg[idx] : 0;
    s[t] = v;
    __syncthreads();
    for (int off = 1; off < 1024; off <<= 1) {
        int tv = (t >= off) ? s[t - off] : 0;
        __syncthreads();
        s[t] += tv;
        __syncthreads();
    }
    if (idx < NN) {
        int ex = g_boff[blockIdx.x] + s[t] - v;   // exclusive scan + block offset
        g_rowptr[idx] = ex;
        g_cursor[idx] = ex;
    }
}

// fill CSR; the extra last block runs the input-layer BN finalize instead
__global__ void k_fill_fin(const int* __restrict__ src, const int* __restrict__ dst,
                           const float* __restrict__ g, const float* __restrict__ b) {
    if (blockIdx.x == NBLK_FILL) {
        int c = threadIdx.x;
        if (c < HH) {
            double m = g_bnsum[c] / (double)NN;
            double var = g_bnsum[HH + c] / (double)NN - m * m;
            float sc = g[c] * rsqrtf((float)var + 1e-5f);
            g_scale[c] = sc;
            g_shift[c] = b[c] - (float)m * sc;
        }
        return;
    }
    int e = blockIdx.x * blockDim.x + threadIdx.x;
    if (e < EE) {
        int p = atomicAdd(&g_cursor[dst[e]], 1);
        g_csr[p] = src[e];
    }
}

// ---------------- mean aggregation with fused BN+ReLU (fp16 gather) --------
__global__ void k_agg() {
    if (blockIdx.x == 0) g_bnsum[threadIdx.x] = 0.0;   // 256 threads = 2*HH
    int w = (blockIdx.x * blockDim.x + threadIdx.x) >> 5;
    int lane = threadIdx.x & 31;
    if (w >= NN) return;
    int s0 = g_rowptr[w], s1 = g_rowptr[w + 1];
    int cb = lane * 4;
    float4 sc = *(const float4*)&g_scale[cb];
    float4 sf = *(const float4*)&g_shift[cb];
    float4 acc = make_float4(0.f, 0.f, 0.f, 0.f);
    const __half* hb = g_hh;
    int j = s0;
    for (; j + 4 <= s1; j += 4) {
        int a = g_csr[j], b = g_csr[j + 1], c = g_csr[j + 2], d = g_csr[j + 3];
        float4 va = ld_h4(hb + (size_t)a * HH + cb);
        float4 vb = ld_h4(hb + (size_t)b * HH + cb);
        float4 vc = ld_h4(hb + (size_t)c * HH + cb);
        float4 vd = ld_h4(hb + (size_t)d * HH + cb);
        acc.x += fmaxf(va.x * sc.x + sf.x, 0.f) + fmaxf(vb.x * sc.x + sf.x, 0.f)
               + fmaxf(vc.x * sc.x + sf.x, 0.f) + fmaxf(vd.x * sc.x + sf.x, 0.f);
        acc.y += fmaxf(va.y * sc.y + sf.y, 0.f) + fmaxf(vb.y * sc.y + sf.y, 0.f)
               + fmaxf(vc.y * sc.y + sf.y, 0.f) + fmaxf(vd.y * sc.y + sf.y, 0.f);
        acc.z += fmaxf(va.z * sc.z + sf.z, 0.f) + fmaxf(vb.z * sc.z + sf.z, 0.f)
               + fmaxf(vc.z * sc.z + sf.z, 0.f) + fmaxf(vd.z * sc.z + sf.z, 0.f);
        acc.w += fmaxf(va.w * sc.w + sf.w, 0.f) + fmaxf(vb.w * sc.w + sf.w, 0.f)
               + fmaxf(vc.w * sc.w + sf.w, 0.f) + fmaxf(vd.w * sc.w + sf.w, 0.f);
    }
    for (; j < s1; j++) {
        int a = g_csr[j];
        float4 va = ld_h4(hb + (size_t)a * HH + cb);
        acc.x += fmaxf(va.x * sc.x + sf.x, 0.f);
        acc.y += fmaxf(va.y * sc.y + sf.y, 0.f);
        acc.z += fmaxf(va.z * sc.z + sf.z, 0.f);
        acc.w += fmaxf(va.w * sc.w + sf.w, 0.f);
    }
    float inv = (s1 > s0) ? 1.0f / (float)(s1 - s0) : 0.0f;
    acc.x *= inv; acc.y *= inv; acc.z *= inv; acc.w *= inv;
    *(uint2*)(g_h16 + (size_t)w * HH + cb) = pack_h4(acc);
}

// ---------------- FFMA2 (packed f32x2) SGEMM, register-prefetch ------------
__device__ __forceinline__ unsigned long long pk1(float v) {
    unsigned long long r;
    asm("mov.b64 %0, {%1, %1};" : "=l"(r) : "f"(v));
    return r;
}
__device__ __forceinline__ unsigned long long pk2(float x, float y) {
    unsigned long long r;
    asm("mov.b64 %0, {%1, %2};" : "=l"(r) : "f"(x), "f"(y));
    return r;
}

#define BKG 16
// dual==0: C = Aext @ W1 + bias. Extra blocks (>= NBLK_GEMM) run the edge
//          histogram on dst_h (input-layer launch overlaps CSR hist).
// dual==1: C = g_h16 @ W1 + relu(bn(g_agg)) @ W2 + bias  (phase-0 A is fp16).
// stats==1: accumulate per-column sum/sumsq of C into g_bnsum AND write the
//           fp16 shadow g_hh (both needed iff another SAGE layer follows).
__global__ __launch_bounds__(256, 2) void k_gemm(const float* __restrict__ Aext,
                                                 const float* __restrict__ W1,
                                                 const float* __restrict__ W2,
                                                 const float* __restrict__ bias,
                                                 int dual, int stats,
                                                 const int* __restrict__ dst_h) {
    if (blockIdx.x >= NBLK_GEMM) {
        int e = (blockIdx.x - NBLK_GEMM) * 256 + threadIdx.x;
        if (e < EE) atomicAdd(&g_deg[dst_h[e]], 1);
        return;
    }
    __shared__ unsigned long long As[BKG][130];  // duplicated pairs, 16B-aligned rows
    __shared__ float Ws[BKG][HH];
    __shared__ float sc_s[HH], sf_s[HH];
    int tid = threadIdx.x;
    int tx = tid & 15, ty = tid >> 4;
    int r0 = blockIdx.x * 128;
    unsigned long long acc[32];
#pragma unroll
    for (int i = 0; i < 32; i++) acc[i] = 0ULL;

    if (tid < HH) { sc_s[tid] = g_scale[tid]; sf_s[tid] = g_shift[tid]; }
    __syncthreads();

    int total = dual ? 16 : 8;   // tiles of 16 k-values
    float4 va[2], vw[2];

    // prologue: load tile 0 into registers (dual phase-0 reads fp16 aggregate)
    {
#pragma unroll
        for (int it = 0; it < 2; it++) {
            int f4i = tid + it * 256;
            int row = f4i >> 2, c4 = f4i & 3;
            va[it] = make_float4(0.f, 0.f, 0.f, 0.f);
            if (r0 + row < NN) {
                if (dual)
                    va[it] = ld_h4(g_h16 + (size_t)(r0 + row) * HH + c4 * 4);
                else
                    va[it] = *(const float4*)(Aext + (size_t)(r0 + row) * HH + c4 * 4);
            }
        }
#pragma unroll
        for (int it = 0; it < 2; it++) {
            int f4i = tid + it * 256;
            int k = f4i >> 5, c4 = f4i & 31;
            vw[it] = *(const float4*)(W1 + (size_t)k * HH + c4 * 4);
        }
    }

    for (int t = 0; t < total; t++) {
        int kb = (t & 7) * 16;
        int bn = (dual && t >= 8);
        // --- store tile t (currently in regs) to smem ---
#pragma unroll
        for (int it = 0; it < 2; it++) {
            int f4i = tid + it * 256;
            int row = f4i >> 2, c4 = f4i & 3;
            float4 v = va[it];
            if (bn) {
                float4 scv = *(const float4*)&sc_s[kb + c4 * 4];
                float4 sfv = *(const float4*)&sf_s[kb + c4 * 4];
                v.x = fmaxf(v.x * scv.x + sfv.x, 0.f);
                v.y = fmaxf(v.y * scv.y + sfv.y, 0.f);
                v.z = fmaxf(v.z * scv.z + sfv.z, 0.f);
                v.w = fmaxf(v.w * scv.w + sfv.w, 0.f);
            }
            int k = c4 * 4;
            As[k + 0][row] = pk1(v.x);
            As[k + 1][row] = pk1(v.y);
            As[k + 2][row] = pk1(v.z);
            As[k + 3][row] = pk1(v.w);
        }
#pragma unroll
        for (int it = 0; it < 2; it++) {
            int f4i = tid + it * 256;
            int k = f4i >> 5, c4 = f4i & 31;
            *(float4*)&Ws[k][c4 * 4] = vw[it];
        }
        __syncthreads();

        // --- prefetch tile t+1 into regs (latency hides under compute) ---
        if (t + 1 < total) {
            int tn = t + 1;
            int kbn = (tn & 7) * 16;
            int p0 = (dual && tn < 8);   // phase-0: fp16 aggregate source
            const float* Wp = (dual && tn >= 8) ? W2 : W1;
#pragma unroll
            for (int it = 0; it < 2; it++) {
                int f4i = tid + it * 256;
                int row = f4i >> 2, c4 = f4i & 3;
                va[it] = make_float4(0.f, 0.f, 0.f, 0.f);
                if (r0 + row < NN) {
                    if (p0)
                        va[it] = ld_h4(g_h16 + (size_t)(r0 + row) * HH + kbn + c4 * 4);
                    else if (dual)
                        va[it] = *(const float4*)(g_agg + (size_t)(r0 + row) * HH + kbn + c4 * 4);
                    else
                        va[it] = *(const float4*)(Aext + (size_t)(r0 + row) * HH + kbn + c4 * 4);
                }
            }
#pragma unroll
            for (int it = 0; it < 2; it++) {
                int f4i = tid + it * 256;
                int k = f4i >> 5, c4 = f4i & 31;
                vw[it] = *(const float4*)(Wp + (size_t)(kbn + k) * HH + c4 * 4);
            }
        }

        // --- compute tile t ---
#pragma unroll
        for (int k = 0; k < BKG; k++) {
            ulonglong2 a01 = *(const ulonglong2*)&As[k][ty * 8 + 0];
            ulonglong2 a23 = *(const ulonglong2*)&As[k][ty * 8 + 2];
            ulonglong2 a45 = *(const ulonglong2*)&As[k][ty * 8 + 4];
            ulonglong2 a67 = *(const ulonglong2*)&As[k][ty * 8 + 6];
            ulonglong2 bp01 = *(const ulonglong2*)&Ws[k][tx * 8];
            ulonglong2 bp23 = *(const ulonglong2*)&Ws[k][tx * 8 + 4];
            unsigned long long a[8] = {a01.x, a01.y, a23.x, a23.y,
                                       a45.x, a45.y, a67.x, a67.y};
#pragma unroll
            for (int i = 0; i < 8; i++) {
                asm("fma.rn.f32x2 %0, %1, %2, %0;" : "+l"(acc[i * 4 + 0]) : "l"(a[i]), "l"(bp01.x));
                asm("fma.rn.f32x2 %0, %1, %2, %0;" : "+l"(acc[i * 4 + 1]) : "l"(a[i]), "l"(bp01.y));
                asm("fma.rn.f32x2 %0, %1, %2, %0;" : "+l"(acc[i * 4 + 2]) : "l"(a[i]), "l"(bp23.x));
                asm("fma.rn.f32x2 %0, %1, %2, %0;" : "+l"(acc[i * 4 + 3]) : "l"(a[i]), "l"(bp23.y));
            }
        }
        __syncthreads();
    }

    // --- epilogue: bias + write fp32 (+ fp16 shadow + BN stats when stats) --
    float bcol[8];
#pragma unroll
    for (int j = 0; j < 8; j++) bcol[j] = bias[tx * 8 + j];
    float csum[8], csq[8];
#pragma unroll
    for (int j = 0; j < 8; j++) { csum[j] = 0.f; csq[j] = 0.f; }
#pragma unroll
    for (int i = 0; i < 8; i++) {
        int r = r0 + ty * 8 + i;
        float o[8];
#pragma unroll
        for (int j = 0; j < 4; j++)
            asm("mov.b64 {%0, %1}, %2;" : "=f"(o[2 * j]), "=f"(o[2 * j + 1]) : "l"(acc[i * 4 + j]));
#pragma unroll
        for (int j = 0; j < 8; j++) o[j] += bcol[j];
        if (r < NN) {
            float4 v0 = make_float4(o[0], o[1], o[2], o[3]);
            float4 v1 = make_float4(o[4], o[5], o[6], o[7]);
            *(float4*)(g_agg + (size_t)r * HH + tx * 8) = v0;
            *(float4*)(g_agg + (size_t)r * HH + tx * 8 + 4) = v1;
            if (stats) {
                uint4 hv;
                unsigned int* hp = (unsigned int*)&hv;
#pragma unroll
                for (int j = 0; j < 4; j++) {
                    unsigned short lo = __half_as_ushort(__float2half_rn(o[2 * j]));
                    unsigned short hi = __half_as_ushort(__float2half_rn(o[2 * j + 1]));
                    hp[j] = ((unsigned int)hi << 16) | lo;
                }
                *(uint4*)(g_hh + (size_t)r * HH + tx * 8) = hv;
#pragma unroll
                for (int j = 0; j < 8; j++) { csum[j] += o[j]; csq[j] += o[j] * o[j]; }
            }
        }
    }
    if (stats) {
        // reduce per-column partials across ty via As (free after loop's sync)
        float* red = (float*)As;   // 16 * 256 floats = 16KB <= sizeof(As)
#pragma unroll
        for (int j = 0; j < 8; j++) {
            red[ty * 256 + tx * 8 + j] = csum[j];
            red[ty * 256 + 128 + tx * 8 + j] = csq[j];
        }
        __syncthreads();
        if (tid < HH) {
            float s = 0.f, q = 0.f;
#pragma unroll
            for (int t = 0; t < 16; t++) {
                s += red[t * 256 + tid];
                q += red[t * 256 + 128 + tid];
            }
            atomicAdd(&g_bnsum[tid], (double)s);
            atomicAdd(&g_bnsum[HH + tid], (double)q);
        }
    }
}

// ---------------- BN finalize (layer version) ------------------------------
__global__ void k_finalize(const float* __restrict__ g, const float* __restrict__ b) {
    int c = threadIdx.x;
    if (c < HH) {
        double m = g_bnsum[c] / (double)NN;
        double var = g_bnsum[HH + c] / (double)NN - m * m;
        float sc = g[c] * rsqrtf((float)var + 1e-5f);
        g_scale[c] = sc;
        g_shift[c] = b[c] - (float)m * sc;
    }
}

// ---------------- final projection (N x 128) @ (128 x 40), f32x2 -----------
// 256 threads: tx = tid&3 (5 col-pairs each), ty = tid>>2 (2 rows each).
__global__ __launch_bounds__(256) void k_out(const float* __restrict__ Wo,
                                             const float* __restrict__ bo,
                                             float* __restrict__ out) {
    __shared__ unsigned long long Wsd[HH * 20];   // [k][20 col-pairs], 20.5KB
    __shared__ unsigned long long As[16 * 128];   // [k][row] dup pairs, 16KB
    int tid = threadIdx.x;
    int tx = tid & 3, ty = tid >> 2;
    int r0 = blockIdx.x * 128;
    // stage all weights as packed col pairs
    for (int i = tid; i < HH * 20; i += 256) {
        int k = i / 20, p = i % 20;
        Wsd[i] = pk2(Wo[k * CCOUT + p * 2], Wo[k * CCOUT + p * 2 + 1]);
    }
    unsigned long long acc[2][5];
#pragma unroll
    for (int r = 0; r < 2; r++)
#pragma unroll
        for (int p = 0; p < 5; p++) acc[r][p] = 0ULL;

    for (int kb = 0; kb < HH; kb += 16) {
        __syncthreads();
#pragma unroll
        for (int it = 0; it < 2; it++) {
            int f4i = tid + it * 256;
            int row = f4i >> 2, c4 = f4i & 3;
            float4 v = make_float4(0.f, 0.f, 0.f, 0.f);
            if (r0 + row < NN)
                v = *(const float4*)(g_agg + (size_t)(r0 + row) * HH + kb + c4 * 4);
            As[(c4 * 4 + 0) * 128 + row] = pk1(v.x);
            As[(c4 * 4 + 1) * 128 + row] = pk1(v.y);
            As[(c4 * 4 + 2) * 128 + row] = pk1(v.z);
            As[(c4 * 4 + 3) * 128 + row] = pk1(v.w);
        }
        __syncthreads();
#pragma unroll
        for (int k = 0; k < 16; k++) {
            ulonglong2 a = *(const ulonglong2*)&As[k * 128 + ty * 2];
            const unsigned long long* brow = &Wsd[(kb + k) * 20 + tx * 5];
#pragma unroll
            for (int p = 0; p < 5; p++) {
                unsigned long long b = brow[p];
                asm("fma.rn.f32x2 %0, %1, %2, %0;" : "+l"(acc[0][p]) : "l"(a.x), "l"(b));
                asm("fma.rn.f32x2 %0, %1, %2, %0;" : "+l"(acc[1][p]) : "l"(a.y), "l"(b));
            }
        }
    }
#pragma unroll
    for (int r = 0; r < 2; r++) {
        int row = r0 + ty * 2 + r;
        if (row < NN) {
#pragma unroll
            for (int p = 0; p < 5; p++) {
                float lo, hi;
                asm("mov.b64 {%0, %1}, %2;" : "=f"(lo), "=f"(hi) : "l"(acc[r][p]));
                int c = tx * 10 + p * 2;
                float2 v = make_float2(lo + bo[c], hi + bo[c + 1]);
                *(float2*)(out + (size_t)row * CCOUT + c) = v;
            }
        }
    }
}

// ---------------- driver ---------------------------------------------------
extern "C" void kernel_launch(void* const* d_in, const int* in_sizes, int n_in,
                              void* d_out, int out_size) {
    const float* x       = (const float*)d_in[0];
    const float* W_in    = (const float*)d_in[1];
    const float* b_in    = (const float*)d_in[2];
    const float* g_in    = (const float*)d_in[3];
    const float* beta_in = (const float*)d_in[4];
    const float* Wl      = (const float*)d_in[5];
    const float* bl      = (const float*)d_in[6];
    const float* Wr      = (const float*)d_in[7];
    const float* gbn     = (const float*)d_in[8];
    const float* bbn     = (const float*)d_in[9];
    const float* W_out   = (const float*)d_in[10];
    const float* b_out   = (const float*)d_in[11];
    const int*   ei      = (const int*)d_in[12];
    const int* src = ei;
    const int* dst = ei + EE;
    float* out = (float*)d_out;

    // zero degree histogram + input-layer BN accumulators
    k_zero0<<<(NN + 255) / 256, 256>>>();

    // Input-layer GEMM (fused column stats + fp16 shadow) with edge histogram
    // riding on the same grid's extra blocks.
    k_gemm<<<NBLK_GEMM + NBLK_HIST, 256>>>(x, W_in, nullptr, b_in, 0, 1, dst);

    // CSR prefix-sum chain; fill kernel's extra block finalizes input BN.
    k_bsum<<<SB, 256>>>();
    k_bscan<<<1, 128>>>();
    k_scan<<<SB, 1024>>>();
    k_fill_fin<<<NBLK_FILL + 1, 256>>>(src, dst, g_in, beta_in);

    // SAGE layers: k_agg gathers the fp16 shadow, applies BN+ReLU in-flight,
    // and writes the fp16 aggregate; the GEMM reads the fp16 aggregate for the
    // Wl term and applies BN+ReLU (fp32) to the root term, emitting the next
    // fp16 shadow + BN stats when another layer follows.
    for (int i = 0; i < 4; i++) {
        k_agg<<<(NN * 32 + 255) / 256, 256>>>();
        k_gemm<<<NBLK_GEMM, 256>>>(nullptr,
                                   Wl + (size_t)i * HH * HH,
                                   Wr + (size_t)i * HH * HH,
                                   bl + (size_t)i * HH, 1, (i < 3) ? 1 : 0, nullptr);
        if (i < 3) k_finalize<<<1, 128>>>(gbn + i * HH, bbn + i * HH);
    }

    // Output projection from the raw (no BN) last-layer activations in g_agg
    k_out<<<NBLK_GEMM, 256>>>(W_out, b_out, out);
}

// round 16
// speedup vs baseline: 1.0279x; 1.0279x over previous
#include <cuda_runtime.h>
#include <cuda_fp16.h>
#include <cstdint>
#include <cstddef>

// Problem constants (fixed by the dataset)
#define NN 100000
#define EE 1600000
#define HH 128
#define CCOUT 40
#define SB 98            // ceil(NN/1024) scan blocks
#define NBLK_GEMM 782    // ceil(NN/128)
#define NBLK_HIST 6250   // EE/256
#define NBLK_FILL 6250   // EE/256

// ---------------- scratch (device globals; no allocation allowed) ----------
// Per-layer live set: g_hh (25MB gather) + g_h (51MB) + csr (6.4MB) ~ 82MB
// << 126MB L2. g_agg (fp32) is written only by the LAST dual GEMM (k_out
// input); stats-layer GEMMs hand off solely through the fp16 shadow g_hh.
__device__ float g_h[(size_t)NN * HH];     // aggregate buffer (k_agg output, fp32)
__device__ float g_agg[(size_t)NN * HH];   // final-layer pre-BN output (k_out input)
__device__ __half g_hh[(size_t)NN * HH];   // fp16 shadow of pre-BN output (gather + root source)
__device__ int   g_deg[NN];
__device__ int   g_rowptr[NN + 1];
__device__ int   g_cursor[NN];
__device__ int   g_csr[EE];
__device__ int   g_bsum[SB];
__device__ int   g_boff[SB];
__device__ double g_bnsum[2 * HH];
__device__ float g_scale[HH];
__device__ float g_shift[HH];

// ---------------- fp16 helpers ---------------------------------------------
__device__ __forceinline__ float4 ld_h4(const __half* p) {
    uint2 u = *(const uint2*)p;
    __half2 a = *reinterpret_cast<const __half2*>(&u.x);
    __half2 b = *reinterpret_cast<const __half2*>(&u.y);
    float2 fa = __half22float2(a), fb = __half22float2(b);
    return make_float4(fa.x, fa.y, fb.x, fb.y);
}

// ---------------- CSR build ------------------------------------------------
// zero g_deg; block 0 also zeroes g_bnsum (for the input-layer GEMM stats)
__global__ void k_zero0() {
    int i = blockIdx.x * blockDim.x + threadIdx.x;
    if (i < NN) g_deg[i] = 0;
    if (blockIdx.x == 0) g_bnsum[threadIdx.x] = 0.0;   // 256 threads = 2*HH
}

__global__ void k_bsum() {
    __shared__ int red[256];
    int b = blockIdx.x, t = threadIdx.x;
    int s = 0;
#pragma unroll
    for (int it = 0; it < 4; it++) {
        int idx = b * 1024 + it * 256 + t;
        if (idx < NN) s += g_deg[idx];
    }
    red[t] = s;
    __syncthreads();
    for (int off = 128; off > 0; off >>= 1) {
        if (t < off) red[t] += red[t + off];
        __syncthreads();
    }
    if (t == 0) g_bsum[b] = red[0];
}

// parallel scan of the 98 block sums
__global__ void k_bscan() {
    __shared__ int s[128];
    int t = threadIdx.x;
    int v = (t < SB) ? g_bsum[t] : 0;
    s[t] = v;
    __syncthreads();
    for (int off = 1; off < 128; off <<= 1) {
        int tv = (t >= off) ? s[t - off] : 0;
        __syncthreads();
        s[t] += tv;
        __syncthreads();
    }
    if (t < SB) g_boff[t] = s[t] - v;   // exclusive
    if (t == 0) g_rowptr[NN] = EE;
}

__global__ void k_scan() {
    __shared__ int s[1024];
    int t = threadIdx.x;
    int idx = blockIdx.x * 1024 + t;
    int v = (idx < NN) ? g_deg[idx] : 0;
    s[t] = v;
    __syncthreads();
    for (int off = 1; off < 1024; off <<= 1) {
        int tv = (t >= off) ? s[t - off] : 0;
        __syncthreads();
        s[t] += tv;
        __syncthreads();
    }
    if (idx < NN) {
        int ex = g_boff[blockIdx.x] + s[t] - v;   // exclusive scan + block offset
        g_rowptr[idx] = ex;
        g_cursor[idx] = ex;
    }
}

// fill CSR; the extra last block runs the input-layer BN finalize instead
__global__ void k_fill_fin(const int* __restrict__ src, const int* __restrict__ dst,
                           const float* __restrict__ g, const float* __restrict__ b) {
    if (blockIdx.x == NBLK_FILL) {
        int c = threadIdx.x;
        if (c < HH) {
            double m = g_bnsum[c] / (double)NN;
            double var = g_bnsum[HH + c] / (double)NN - m * m;
            float sc = g[c] * rsqrtf((float)var + 1e-5f);
            g_scale[c] = sc;
            g_shift[c] = b[c] - (float)m * sc;
        }
        return;
    }
    int e = blockIdx.x * blockDim.x + threadIdx.x;
    if (e < EE) {
        int p = atomicAdd(&g_cursor[dst[e]], 1);
        g_csr[p] = src[e];
    }
}

// ---------------- mean aggregation with fused BN+ReLU (fp16 gather) --------
__global__ void k_agg() {
    if (blockIdx.x == 0) g_bnsum[threadIdx.x] = 0.0;   // 256 threads = 2*HH
    int w = (blockIdx.x * blockDim.x + threadIdx.x) >> 5;
    int lane = threadIdx.x & 31;
    if (w >= NN) return;
    int s0 = g_rowptr[w], s1 = g_rowptr[w + 1];
    int cb = lane * 4;
    float4 sc = *(const float4*)&g_scale[cb];
    float4 sf = *(const float4*)&g_shift[cb];
    float4 acc = make_float4(0.f, 0.f, 0.f, 0.f);
    const __half* hb = g_hh;
    int j = s0;
    for (; j + 4 <= s1; j += 4) {
        int a = g_csr[j], b = g_csr[j + 1], c = g_csr[j + 2], d = g_csr[j + 3];
        float4 va = ld_h4(hb + (size_t)a * HH + cb);
        float4 vb = ld_h4(hb + (size_t)b * HH + cb);
        float4 vc = ld_h4(hb + (size_t)c * HH + cb);
        float4 vd = ld_h4(hb + (size_t)d * HH + cb);
        acc.x += fmaxf(va.x * sc.x + sf.x, 0.f) + fmaxf(vb.x * sc.x + sf.x, 0.f)
               + fmaxf(vc.x * sc.x + sf.x, 0.f) + fmaxf(vd.x * sc.x + sf.x, 0.f);
        acc.y += fmaxf(va.y * sc.y + sf.y, 0.f) + fmaxf(vb.y * sc.y + sf.y, 0.f)
               + fmaxf(vc.y * sc.y + sf.y, 0.f) + fmaxf(vd.y * sc.y + sf.y, 0.f);
        acc.z += fmaxf(va.z * sc.z + sf.z, 0.f) + fmaxf(vb.z * sc.z + sf.z, 0.f)
               + fmaxf(vc.z * sc.z + sf.z, 0.f) + fmaxf(vd.z * sc.z + sf.z, 0.f);
        acc.w += fmaxf(va.w * sc.w + sf.w, 0.f) + fmaxf(vb.w * sc.w + sf.w, 0.f)
               + fmaxf(vc.w * sc.w + sf.w, 0.f) + fmaxf(vd.w * sc.w + sf.w, 0.f);
    }
    for (; j < s1; j++) {
        int a = g_csr[j];
        float4 va = ld_h4(hb + (size_t)a * HH + cb);
        acc.x += fmaxf(va.x * sc.x + sf.x, 0.f);
        acc.y += fmaxf(va.y * sc.y + sf.y, 0.f);
        acc.z += fmaxf(va.z * sc.z + sf.z, 0.f);
        acc.w += fmaxf(va.w * sc.w + sf.w, 0.f);
    }
    float inv = (s1 > s0) ? 1.0f / (float)(s1 - s0) : 0.0f;
    acc.x *= inv; acc.y *= inv; acc.z *= inv; acc.w *= inv;
    *(float4*)(g_h + (size_t)w * HH + cb) = acc;
}

// ---------------- FFMA2 (packed f32x2) SGEMM, register-prefetch ------------
__device__ __forceinline__ unsigned long long pk1(float v) {
    unsigned long long r;
    asm("mov.b64 %0, {%1, %1};" : "=l"(r) : "f"(v));
    return r;
}
__device__ __forceinline__ unsigned long long pk2(float x, float y) {
    unsigned long long r;
    asm("mov.b64 %0, {%1, %2};" : "=l"(r) : "f"(x), "f"(y));
    return r;
}

#define BKG 16
// dual==0: C = Aext @ W1 + bias. Extra blocks (>= NBLK_GEMM) run the edge
//          histogram on dst_h (input-layer launch overlaps CSR hist).
// dual==1: C = g_h @ W1 + relu(bn(g_hh)) @ W2 + bias (root term from shadow).
// stats==1: C is handed to the next layer ONLY via the fp16 shadow g_hh
//           (+ per-column sum/sumsq into g_bnsum); fp32 g_agg not written.
// stats==0: final layer -- write fp32 g_agg for k_out, no shadow/stats.
__global__ __launch_bounds__(256, 2) void k_gemm(const float* __restrict__ Aext,
                                                 const float* __restrict__ W1,
                                                 const float* __restrict__ W2,
                                                 const float* __restrict__ bias,
                                                 int dual, int stats,
                                                 const int* __restrict__ dst_h) {
    if (blockIdx.x >= NBLK_GEMM) {
        int e = (blockIdx.x - NBLK_GEMM) * 256 + threadIdx.x;
        if (e < EE) atomicAdd(&g_deg[dst_h[e]], 1);
        return;
    }
    __shared__ unsigned long long As[BKG][130];  // duplicated pairs, 16B-aligned rows
    __shared__ float Ws[BKG][HH];
    __shared__ float sc_s[HH], sf_s[HH];
    int tid = threadIdx.x;
    int tx = tid & 15, ty = tid >> 4;
    int r0 = blockIdx.x * 128;
    unsigned long long acc[32];
#pragma unroll
    for (int i = 0; i < 32; i++) acc[i] = 0ULL;

    if (tid < HH) { sc_s[tid] = g_scale[tid]; sf_s[tid] = g_shift[tid]; }
    __syncthreads();

    int total = dual ? 16 : 8;   // tiles of 16 k-values
    float4 va[2], vw[2];

    // prologue: load tile 0 into registers
    {
        const float* Ap = dual ? (const float*)g_h : Aext;
#pragma unroll
        for (int it = 0; it < 2; it++) {
            int f4i = tid + it * 256;
            int row = f4i >> 2, c4 = f4i & 3;
            va[it] = make_float4(0.f, 0.f, 0.f, 0.f);
            if (r0 + row < NN)
                va[it] = *(const float4*)(Ap + (size_t)(r0 + row) * HH + c4 * 4);
        }
#pragma unroll
        for (int it = 0; it < 2; it++) {
            int f4i = tid + it * 256;
            int k = f4i >> 5, c4 = f4i & 31;
            vw[it] = *(const float4*)(W1 + (size_t)k * HH + c4 * 4);
        }
    }

    for (int t = 0; t < total; t++) {
        int kb = (t & 7) * 16;
        int bn = (dual && t >= 8);
        // --- store tile t (currently in regs) to smem ---
#pragma unroll
        for (int it = 0; it < 2; it++) {
            int f4i = tid + it * 256;
            int row = f4i >> 2, c4 = f4i & 3;
            float4 v = va[it];
            if (bn) {
                float4 scv = *(const float4*)&sc_s[kb + c4 * 4];
                float4 sfv = *(const float4*)&sf_s[kb + c4 * 4];
                v.x = fmaxf(v.x * scv.x + sfv.x, 0.f);
                v.y = fmaxf(v.y * scv.y + sfv.y, 0.f);
                v.z = fmaxf(v.z * scv.z + sfv.z, 0.f);
                v.w = fmaxf(v.w * scv.w + sfv.w, 0.f);
            }
            int k = c4 * 4;
            As[k + 0][row] = pk1(v.x);
            As[k + 1][row] = pk1(v.y);
            As[k + 2][row] = pk1(v.z);
            As[k + 3][row] = pk1(v.w);
        }
#pragma unroll
        for (int it = 0; it < 2; it++) {
            int f4i = tid + it * 256;
            int k = f4i >> 5, c4 = f4i & 31;
            *(float4*)&Ws[k][c4 * 4] = vw[it];
        }
        __syncthreads();

        // --- prefetch tile t+1 into regs (latency hides under compute) ---
        if (t + 1 < total) {
            int tn = t + 1;
            int kbn = (tn & 7) * 16;
            int p1 = (dual && tn >= 8);   // phase-1: fp16 shadow source
            const float* Wp = p1 ? W2 : W1;
#pragma unroll
            for (int it = 0; it < 2; it++) {
                int f4i = tid + it * 256;
                int row = f4i >> 2, c4 = f4i & 3;
                va[it] = make_float4(0.f, 0.f, 0.f, 0.f);
                if (r0 + row < NN) {
                    if (p1)
                        va[it] = ld_h4(g_hh + (size_t)(r0 + row) * HH + kbn + c4 * 4);
                    else if (dual)
                        va[it] = *(const float4*)(g_h + (size_t)(r0 + row) * HH + kbn + c4 * 4);
                    else
                        va[it] = *(const float4*)(Aext + (size_t)(r0 + row) * HH + kbn + c4 * 4);
                }
            }
#pragma unroll
            for (int it = 0; it < 2; it++) {
                int f4i = tid + it * 256;
                int k = f4i >> 5, c4 = f4i & 31;
                vw[it] = *(const float4*)(Wp + (size_t)(kbn + k) * HH + c4 * 4);
            }
        }

        // --- compute tile t ---
#pragma unroll
        for (int k = 0; k < BKG; k++) {
            ulonglong2 a01 = *(const ulonglong2*)&As[k][ty * 8 + 0];
            ulonglong2 a23 = *(const ulonglong2*)&As[k][ty * 8 + 2];
            ulonglong2 a45 = *(const ulonglong2*)&As[k][ty * 8 + 4];
            ulonglong2 a67 = *(const ulonglong2*)&As[k][ty * 8 + 6];
            ulonglong2 bp01 = *(const ulonglong2*)&Ws[k][tx * 8];
            ulonglong2 bp23 = *(const ulonglong2*)&Ws[k][tx * 8 + 4];
            unsigned long long a[8] = {a01.x, a01.y, a23.x, a23.y,
                                       a45.x, a45.y, a67.x, a67.y};
#pragma unroll
            for (int i = 0; i < 8; i++) {
                asm("fma.rn.f32x2 %0, %1, %2, %0;" : "+l"(acc[i * 4 + 0]) : "l"(a[i]), "l"(bp01.x));
                asm("fma.rn.f32x2 %0, %1, %2, %0;" : "+l"(acc[i * 4 + 1]) : "l"(a[i]), "l"(bp01.y));
                asm("fma.rn.f32x2 %0, %1, %2, %0;" : "+l"(acc[i * 4 + 2]) : "l"(a[i]), "l"(bp23.x));
                asm("fma.rn.f32x2 %0, %1, %2, %0;" : "+l"(acc[i * 4 + 3]) : "l"(a[i]), "l"(bp23.y));
            }
        }
        __syncthreads();
    }

    // --- epilogue: bias + handoff ---
    //   stats==1: fp16 shadow + BN column stats (no fp32 g_agg write)
    //   stats==0: fp32 g_agg for k_out
    float bcol[8];
#pragma unroll
    for (int j = 0; j < 8; j++) bcol[j] = bias[tx * 8 + j];
    float csum[8], csq[8];
#pragma unroll
    for (int j = 0; j < 8; j++) { csum[j] = 0.f; csq[j] = 0.f; }
#pragma unroll
    for (int i = 0; i < 8; i++) {
        int r = r0 + ty * 8 + i;
        float o[8];
#pragma unroll
        for (int j = 0; j < 4; j++)
            asm("mov.b64 {%0, %1}, %2;" : "=f"(o[2 * j]), "=f"(o[2 * j + 1]) : "l"(acc[i * 4 + j]));
#pragma unroll
        for (int j = 0; j < 8; j++) o[j] += bcol[j];
        if (r < NN) {
            if (stats) {
                uint4 hv;
                unsigned int* hp = (unsigned int*)&hv;
#pragma unroll
                for (int j = 0; j < 4; j++) {
                    unsigned short lo = __half_as_ushort(__float2half_rn(o[2 * j]));
                    unsigned short hi = __half_as_ushort(__float2half_rn(o[2 * j + 1]));
                    hp[j] = ((unsigned int)hi << 16) | lo;
                }
                *(uint4*)(g_hh + (size_t)r * HH + tx * 8) = hv;
#pragma unroll
                for (int j = 0; j < 8; j++) { csum[j] += o[j]; csq[j] += o[j] * o[j]; }
            } else {
                float4 v0 = make_float4(o[0], o[1], o[2], o[3]);
                float4 v1 = make_float4(o[4], o[5], o[6], o[7]);
                *(float4*)(g_agg + (size_t)r * HH + tx * 8) = v0;
                *(float4*)(g_agg + (size_t)r * HH + tx * 8 + 4) = v1;
            }
        }
    }
    if (stats) {
        // reduce per-column partials across ty via As (free after loop's sync)
        float* red = (float*)As;   // 16 * 256 floats = 16KB <= sizeof(As)
#pragma unroll
        for (int j = 0; j < 8; j++) {
            red[ty * 256 + tx * 8 + j] = csum[j];
            red[ty * 256 + 128 + tx * 8 + j] = csq[j];
        }
        __syncthreads();
        if (tid < HH) {
            float s = 0.f, q = 0.f;
#pragma unroll
            for (int t = 0; t < 16; t++) {
                s += red[t * 256 + tid];
                q += red[t * 256 + 128 + tid];
            }
            atomicAdd(&g_bnsum[tid], (double)s);
            atomicAdd(&g_bnsum[HH + tid], (double)q);
        }
    }
}

// ---------------- BN finalize (layer version) ------------------------------
__global__ void k_finalize(const float* __restrict__ g, const float* __restrict__ b) {
    int c = threadIdx.x;
    if (c < HH) {
        double m = g_bnsum[c] / (double)NN;
        double var = g_bnsum[HH + c] / (double)NN - m * m;
        float sc = g[c] * rsqrtf((float)var + 1e-5f);
        g_scale[c] = sc;
        g_shift[c] = b[c] - (float)m * sc;
    }
}

// ---------------- final projection (N x 128) @ (128 x 40), f32x2 -----------
// 256 threads: tx = tid&3 (5 col-pairs each), ty = tid>>2 (2 rows each).
__global__ __launch_bounds__(256) void k_out(const float* __restrict__ Wo,
                                             const float* __restrict__ bo,
                                             float* __restrict__ out) {
    __shared__ unsigned long long Wsd[HH * 20];   // [k][20 col-pairs], 20.5KB
    __shared__ unsigned long long As[16 * 128];   // [k][row] dup pairs, 16KB
    int tid = threadIdx.x;
    int tx = tid & 3, ty = tid >> 2;
    int r0 = blockIdx.x * 128;
    // stage all weights as packed col pairs
    for (int i = tid; i < HH * 20; i += 256) {
        int k = i / 20, p = i % 20;
        Wsd[i] = pk2(Wo[k * CCOUT + p * 2], Wo[k * CCOUT + p * 2 + 1]);
    }
    unsigned long long acc[2][5];
#pragma unroll
    for (int r = 0; r < 2; r++)
#pragma unroll
        for (int p = 0; p < 5; p++) acc[r][p] = 0ULL;

    for (int kb = 0; kb < HH; kb += 16) {
        __syncthreads();
#pragma unroll
        for (int it = 0; it < 2; it++) {
            int f4i = tid + it * 256;
            int row = f4i >> 2, c4 = f4i & 3;
            float4 v = make_float4(0.f, 0.f, 0.f, 0.f);
            if (r0 + row < NN)
                v = *(const float4*)(g_agg + (size_t)(r0 + row) * HH + kb + c4 * 4);
            As[(c4 * 4 + 0) * 128 + row] = pk1(v.x);
            As[(c4 * 4 + 1) * 128 + row] = pk1(v.y);
            As[(c4 * 4 + 2) * 128 + row] = pk1(v.z);
            As[(c4 * 4 + 3) * 128 + row] = pk1(v.w);
        }
        __syncthreads();
#pragma unroll
        for (int k = 0; k < 16; k++) {
            ulonglong2 a = *(const ulonglong2*)&As[k * 128 + ty * 2];
            const unsigned long long* brow = &Wsd[(kb + k) * 20 + tx * 5];
#pragma unroll
            for (int p = 0; p < 5; p++) {
                unsigned long long b = brow[p];
                asm("fma.rn.f32x2 %0, %1, %2, %0;" : "+l"(acc[0][p]) : "l"(a.x), "l"(b));
                asm("fma.rn.f32x2 %0, %1, %2, %0;" : "+l"(acc[1][p]) : "l"(a.y), "l"(b));
            }
        }
    }
#pragma unroll
    for (int r = 0; r < 2; r++) {
        int row = r0 + ty * 2 + r;
        if (row < NN) {
#pragma unroll
            for (int p = 0; p < 5; p++) {
                float lo, hi;
                asm("mov.b64 {%0, %1}, %2;" : "=f"(lo), "=f"(hi) : "l"(acc[r][p]));
                int c = tx * 10 + p * 2;
                float2 v = make_float2(lo + bo[c], hi + bo[c + 1]);
                *(float2*)(out + (size_t)row * CCOUT + c) = v;
            }
        }
    }
}

// ---------------- driver ---------------------------------------------------
extern "C" void kernel_launch(void* const* d_in, const int* in_sizes, int n_in,
                              void* d_out, int out_size) {
    const float* x       = (const float*)d_in[0];
    const float* W_in    = (const float*)d_in[1];
    const float* b_in    = (const float*)d_in[2];
    const float* g_in    = (const float*)d_in[3];
    const float* beta_in = (const float*)d_in[4];
    const float* Wl      = (const float*)d_in[5];
    const float* bl      = (const float*)d_in[6];
    const float* Wr      = (const float*)d_in[7];
    const float* gbn     = (const float*)d_in[8];
    const float* bbn     = (const float*)d_in[9];
    const float* W_out   = (const float*)d_in[10];
    const float* b_out   = (const float*)d_in[11];
    const int*   ei      = (const int*)d_in[12];
    const int* src = ei;
    const int* dst = ei + EE;
    float* out = (float*)d_out;

    // zero degree histogram + input-layer BN accumulators
    k_zero0<<<(NN + 255) / 256, 256>>>();

    // Input-layer GEMM (fp16 shadow + fused column stats) with edge histogram
    // riding on the same grid's extra blocks.
    k_gemm<<<NBLK_GEMM + NBLK_HIST, 256>>>(x, W_in, nullptr, b_in, 0, 1, dst);

    // CSR prefix-sum chain; fill kernel's extra block finalizes input BN.
    k_bsum<<<SB, 256>>>();
    k_bscan<<<1, 128>>>();
    k_scan<<<SB, 1024>>>();
    k_fill_fin<<<NBLK_FILL + 1, 256>>>(src, dst, g_in, beta_in);

    // SAGE layers: k_agg gathers the fp16 shadow with BN+ReLU in-flight and
    // writes the fp32 aggregate; the GEMM takes the aggregate (fp32) and the
    // root term (fp16 shadow, BN+ReLU in staging), emitting the next shadow +
    // stats -- or, on the last layer, the fp32 pre-output for k_out.
    for (int i = 0; i < 4; i++) {
        k_agg<<<(NN * 32 + 255) / 256, 256>>>();
        k_gemm<<<NBLK_GEMM, 256>>>(nullptr,
                                   Wl + (size_t)i * HH * HH,
                                   Wr + (size_t)i * HH * HH,
                                   bl + (size_t)i * HH, 1, (i < 3) ? 1 : 0, nullptr);
        if (i < 3) k_finalize<<<1, 128>>>(gbn + i * HH, bbn + i * HH);
    }

    // Output projection from the raw (no BN) last-layer activations in g_agg
    k_out<<<NBLK_GEMM, 256>>>(W_out, b_out, out);
}